// round 16
// baseline (speedup 1.0000x reference)
#include <cuda_runtime.h>
#include <cuda_bf16.h>
#include <math.h>
#include <stdint.h>

// ---------------------------------------------------------------------------
// VQ-VAE forward — implicit bf16-split mma.sync GEMM over NHWC activations.
// 512-thread CTAs (16 warps, 32x32 warp tiles) for latency hiding.
// 2-plane/3-product bulk; 3-plane/6-product conv1 + VQ scores.
// B=32, CIN=3, IMG=128, D=256, K=512. Latent 32x32.
// ---------------------------------------------------------------------------

#define N_LAT 32768      // B * 32 * 32
#define N_HALF 131072    // B * 64 * 64
#define WPLANE 5242880   // weight plane stride (elements)

// ---- scratch (device globals; allocation is forbidden) ----
static __device__ __nv_bfloat16 g_colh[402653184]; // bf16 activation arena
static __device__ __nv_bfloat16 g_wtsh[15728640];  // 3 planes x 5242880
static __device__ float g_h2[8388608];     // h2 fp32 NHWC
static __device__ float g_a[8388608];      // ab fp32 NHWC
static __device__ float g_ze[8388608];     // ze fp32 NHWC
static __device__ float g_zq[8388608];     // zq fp32 NHWC
static __device__ float g_b2[8388608];     // bb fp32 NHWC
static __device__ float g_s[16777216];     // (512, 32768) VQ scores
static __device__ float g_d1[33554432];    // (32,256,64,64) deconv1 out NCHW
static __device__ int   g_idx[32768];
static __device__ float g_enorm[512];
static __device__ float g_wpk[12288];      // deconv2 repacked weights (fp32)
static __device__ float g_part[4096];      // loss partials

// activation offsets in g_colh (elements)
#define H1H   0           // 2 planes, ps 33554432 (NHWC 64x64x256)
#define H2H   67108864    // 2 planes, ps 8388608 (NHWC 32x32x256)
#define TMPH  83886080
#define ABH   100663296
#define ZEH   117440512   // 3 planes
#define ZQH   142606336
#define BBH   159383552
#define COLA  201326592   // conv1 col [n][64], 3 planes, ps 8388608
#define PS_LAT 8388608
#define PS_H1  33554432

// weight offsets within one plane (elements)
#define OFF_C1    0          // 256 x 64
#define OFF_C2    16384      // 256 x 4096 (rs-major)
#define OFF_ER1A  1064960    // 256 x 2304 (rs-major)
#define OFF_ER1B  1654784    // 256 x 256
#define OFF_ER2A  1720320
#define OFF_ER2B  2310144
#define OFF_DR1A  2375680
#define OFF_DR1B  2965504
#define OFF_DR2A  3031040
#define OFF_DR2B  3620864
#define OFF_EMB   3686400    // 512 x 256
#define OFF_DT1   3817472    // 4 x (256 x 1024) tap-major

// ---------------------------------------------------------------------------
// helpers
// ---------------------------------------------------------------------------
__device__ __forceinline__ uint32_t smem_u32(const void* p) {
    uint32_t a;
    asm("{ .reg .u64 t; cvta.to.shared.u64 t, %1; cvt.u32.u64 %0, t; }" : "=r"(a) : "l"(p));
    return a;
}

__device__ __forceinline__ void cp16(uint32_t dst, const void* src) {
    asm volatile("cp.async.cg.shared.global [%0], [%1], 16;" :: "r"(dst), "l"(src));
}

__device__ __forceinline__ void cp16z(uint32_t dst, const void* src, int sz) {
    asm volatile("cp.async.cg.shared.global [%0], [%1], 16, %2;"
                 :: "r"(dst), "l"(src), "r"(sz));
}

__device__ __forceinline__ uint32_t lds32(uint32_t a) {
    uint32_t v;
    asm volatile("ld.shared.b32 %0, [%1];" : "=r"(v) : "r"(a));
    return v;
}

__device__ __forceinline__ void mma16(float* d, const uint32_t* a, const uint32_t* b) {
    asm volatile(
        "mma.sync.aligned.m16n8k16.row.col.f32.bf16.bf16.f32 "
        "{%0,%1,%2,%3}, {%4,%5,%6,%7}, {%8,%9}, {%0,%1,%2,%3};"
        : "+f"(d[0]), "+f"(d[1]), "+f"(d[2]), "+f"(d[3])
        : "r"(a[0]), "r"(a[1]), "r"(a[2]), "r"(a[3]), "r"(b[0]), "r"(b[1]));
}

__device__ __forceinline__ void split3(float v, uint16_t& q0, uint16_t& q1, uint16_t& q2) {
    __nv_bfloat16 h0 = __float2bfloat16(v);
    float r1 = v - __bfloat162float(h0);
    __nv_bfloat16 h1 = __float2bfloat16(r1);
    float r2 = r1 - __bfloat162float(h1);
    __nv_bfloat16 h2 = __float2bfloat16(r2);
    q0 = __bfloat16_as_ushort(h0);
    q1 = __bfloat16_as_ushort(h1);
    q2 = __bfloat16_as_ushort(h2);
}

__device__ __forceinline__ void split2(float v, uint16_t& q0, uint16_t& q1) {
    __nv_bfloat16 h0 = __float2bfloat16(v);
    float r1 = v - __bfloat162float(h0);
    __nv_bfloat16 h1 = __float2bfloat16(r1);
    q0 = __bfloat16_as_ushort(h0);
    q1 = __bfloat16_as_ushort(h1);
}

__device__ __forceinline__ uint32_t pack2(uint16_t lo, uint16_t hi) {
    return (uint32_t)lo | ((uint32_t)hi << 16);
}

// ---------------------------------------------------------------------------
// Implicit bf16x GEMM:  C[m][n] = sum_k A[m][k] * B_im2col[n][k]
//   512 threads: 4x4 warp grid, each warp 32(M) x 32(N); CTA 128x128.
//   A: weight planes, K reordered rs-major (k = rs*Cin + ci).
//   B: NHWC bf16 activation planes; loader computes tap address per k-chunk,
//      OOB rows zero-filled via cp.async src-size 0.
//   full=1: 3 planes / 6 products; full=0: 2 planes / 3 products.
//   epi=0: NHWC out (bf16 planes [+fp32], resid/relu);
//   epi=1: NCHW scatter fp32 (bias/relu) — also VQ rowmajor via params.
// ---------------------------------------------------------------------------
#define GEMM_SMEM_H 184320   // 3 stages * 6 plane slots * 128 rows * 80 B

__global__ void __launch_bounds__(512, 1) gemm_imp(
    const __nv_bfloat16* __restrict__ A3, size_t aStride,
    const __nv_bfloat16* __restrict__ Bb, size_t bStride,
    int M, int K_pad, int full,
    int Cin, int logCPR, int S_t, int oy0, int ox0, int strideIn,
    int Hin, int Win, int logHWo, int logWo,
    int epi, __nv_bfloat16* __restrict__ Dh, size_t dhStride, int dhPlanes,
    float* __restrict__ Df, const float* __restrict__ residf,
    const float* __restrict__ bias, int relu,
    int Hout, int Wout, int sy, int sx, int ry, int rx)
{
    extern __shared__ char smc[];
    const int tid = threadIdx.x;
    const int lane = tid & 31, warp = tid >> 5;
    const int g = lane >> 2, t = lane & 3;
    const int wm = (warp >> 2) << 5;   // 0..96
    const int wn = (warp & 3) << 5;    // 0..96
    const int bm = blockIdx.x << 7;    // M-tile
    const int bn = blockIdx.y << 7;    // pixel tile
    const uint32_t sb = smem_u32(smc);
    const int nk = K_pad >> 5;
    const int np = full ? 3 : 2;
    const int hwmask = (1 << logHWo) - 1;
    const int wmask = (1 << logWo) - 1;

    float acc[2][4][4];
#pragma unroll
    for (int i = 0; i < 2; i++)
#pragma unroll
        for (int j = 0; j < 4; j++)
#pragma unroll
            for (int q = 0; q < 4; q++) acc[i][j][q] = 0.f;

    auto loadStage = [&](int it, int slot) {
        const uint32_t st = sb + slot * 61440;
        const int rs = it >> logCPR;
        const int ci0 = (it & ((1 << logCPR) - 1)) << 5;
        const int dy = rs / S_t + oy0;
        const int dx = rs % S_t + ox0;
        const int k0 = it << 5;
        const int groups = full ? 6 : 4;
#pragma unroll
        for (int j = 0; j < 6; j++) {
            if (j >= groups) break;
            int c = j * 512 + tid;
            int pg0 = c >> 9;
            int pg = full ? pg0 : ((pg0 & 1) + ((pg0 >> 1) * 3));  // 0,1,3,4
            int r  = (c >> 2) & 127;
            int u  = c & 3;
            uint32_t dst = st + pg * 10240 + r * 80 + u * 16;
            if (pg < 3) {
                cp16(dst, A3 + (size_t)pg * aStride + (size_t)(bm + r) * K_pad + k0 + u * 8);
            } else {
                int n = bn + r;
                int b = n >> logHWo;
                int pp = n & hwmask;
                int oy = pp >> logWo, ox = pp & wmask;
                int iy = oy * strideIn + dy, ix = ox * strideIn + dx;
                bool valid = ((unsigned)iy < (unsigned)Hin) && ((unsigned)ix < (unsigned)Win);
                const __nv_bfloat16* src = Bb + (size_t)(pg - 3) * bStride
                    + (size_t)((b * Hin + iy) * Win + ix) * Cin + ci0 + u * 8;
                if (!valid) src = Bb;
                cp16z(dst, src, valid ? 16 : 0);
            }
        }
        asm volatile("cp.async.commit_group;");
    };

    loadStage(0, 0);
    if (nk > 1) loadStage(1, 1);

    for (int it = 0; it < nk; it++) {
        if (it <= nk - 2) asm volatile("cp.async.wait_group 1;");
        else              asm volatile("cp.async.wait_group 0;");
        __syncthreads();
        if (it + 2 < nk) loadStage(it + 2, (it + 2) % 3);

        const uint32_t st = sb + (it % 3) * 61440;
#pragma unroll
        for (int h = 0; h < 2; h++) {
            uint32_t bf[4][3][2];
#pragma unroll
            for (int nt = 0; nt < 4; nt++)
#pragma unroll
                for (int p = 0; p < 3; p++) {
                    if (p >= np) break;
                    uint32_t ad = st + 30720 + p * 10240
                                + (wn + (nt << 3) + g) * 80 + (h << 5) + (t << 2);
                    bf[nt][p][0] = lds32(ad);
                    bf[nt][p][1] = lds32(ad + 16);
                }
#pragma unroll
            for (int mt = 0; mt < 2; mt++) {
                uint32_t af[3][4];
#pragma unroll
                for (int p = 0; p < 3; p++) {
                    if (p >= np) break;
                    uint32_t ad = st + p * 10240
                                + (wm + (mt << 4) + g) * 80 + (h << 5) + (t << 2);
                    af[p][0] = lds32(ad);
                    af[p][1] = lds32(ad + 640);
                    af[p][2] = lds32(ad + 16);
                    af[p][3] = lds32(ad + 656);
                }
#pragma unroll
                for (int nt = 0; nt < 4; nt++) mma16(acc[mt][nt], af[0], bf[nt][0]);
#pragma unroll
                for (int nt = 0; nt < 4; nt++) mma16(acc[mt][nt], af[1], bf[nt][0]);
#pragma unroll
                for (int nt = 0; nt < 4; nt++) mma16(acc[mt][nt], af[0], bf[nt][1]);
                if (full) {
#pragma unroll
                    for (int nt = 0; nt < 4; nt++) mma16(acc[mt][nt], af[1], bf[nt][1]);
#pragma unroll
                    for (int nt = 0; nt < 4; nt++) mma16(acc[mt][nt], af[2], bf[nt][0]);
#pragma unroll
                    for (int nt = 0; nt < 4; nt++) mma16(acc[mt][nt], af[0], bf[nt][2]);
                }
            }
        }
    }

    if (epi == 0) {
        // ---- NHWC epilogue: split planes (+ optional fp32), resid/relu ----
#pragma unroll
        for (int mt = 0; mt < 2; mt++)
#pragma unroll
            for (int half = 0; half < 2; half++) {
                int m = bm + wm + (mt << 4) + g + (half << 3);
#pragma unroll
                for (int nt = 0; nt < 4; nt++)
#pragma unroll
                    for (int j = 0; j < 2; j++) {
                        int n = bn + wn + (nt << 3) + (t << 1) + j;
                        float v = acc[mt][nt][half * 2 + j];
                        size_t o = (size_t)n * M + m;
                        if (residf) v += residf[o];
                        if (relu) v = fmaxf(v, 0.f);
                        if (Df) Df[o] = v;
                        if (dhPlanes == 3) {
                            uint16_t q0, q1, q2;
                            split3(v, q0, q1, q2);
                            Dh[o] = __ushort_as_bfloat16(q0);
                            Dh[dhStride + o] = __ushort_as_bfloat16(q1);
                            Dh[2 * dhStride + o] = __ushort_as_bfloat16(q2);
                        } else {
                            uint16_t q0, q1;
                            split2(v, q0, q1);
                            Dh[o] = __ushort_as_bfloat16(q0);
                            Dh[dhStride + o] = __ushort_as_bfloat16(q1);
                        }
                    }
            }
    } else {
        // ---- NCHW parity scatter (deconv1) / rowmajor (VQ) ----
        const int HWout = Hout * Wout;
#pragma unroll
        for (int mt = 0; mt < 2; mt++)
#pragma unroll
            for (int half = 0; half < 2; half++) {
                int m = bm + wm + (mt << 4) + g + (half << 3);
                float bv = bias ? bias[m] : 0.f;
                int mb = m * HWout;
#pragma unroll
                for (int nt = 0; nt < 4; nt++) {
                    int n = bn + wn + (nt << 3) + (t << 1);
                    int bimg = n >> logHWo;
                    int p = n & hwmask;
                    int yy = p >> logWo, xx = p & wmask;
                    int o = bimg * M * HWout + mb + (yy * sy + ry) * Wout + xx * sx + rx;
                    float v0 = acc[mt][nt][half * 2 + 0] + bv;
                    float v1 = acc[mt][nt][half * 2 + 1] + bv;
                    if (relu) { v0 = fmaxf(v0, 0.f); v1 = fmaxf(v1, 0.f); }
                    Df[o] = v0;
                    Df[o + sx] = v1;
                }
            }
    }
}

// ---------------------------------------------------------------------------
// conv1 im2col: x (NCHW fp32, C=3) -> col [n][64] 3-plane bf16 (k = ci*16+rs)
// ---------------------------------------------------------------------------
__global__ void im2colT_conv_h(const float* __restrict__ in, __nv_bfloat16* __restrict__ colh,
                               size_t planeStride,
                               int C, int Hin, int Win, int logHW, int logW,
                               int RS, int S, int stride, int pad, int K, int K_pad)
{
    __shared__ float s[32][33];
    const int tid = threadIdx.x;
    const int n0 = blockIdx.x << 5, k0 = blockIdx.y << 5;
    const int nl = tid & 31, kr = tid >> 5;
    const int n = n0 + nl;
    const int b = n >> logHW;
    const int p = n & ((1 << logHW) - 1);
    const int oy = p >> logW, ox = p & ((1 << logW) - 1);
#pragma unroll
    for (int pass = 0; pass < 4; pass++) {
        int k = k0 + pass * 8 + kr;
        float v = 0.f;
        if (k < K) {
            int ci = k / RS;
            int rs = k - ci * RS;
            int r = rs / S, ss = rs - r * S;
            int iy = oy * stride - pad + r;
            int ix = ox * stride - pad + ss;
            if ((unsigned)iy < (unsigned)Hin && (unsigned)ix < (unsigned)Win)
                v = in[((b * C + ci) * Hin + iy) * Win + ix];
        }
        s[pass * 8 + kr][nl] = v;
    }
    __syncthreads();
    const int onl = tid >> 3, kq = tid & 7;
    uint16_t q0[4], q1[4], q2[4];
#pragma unroll
    for (int j = 0; j < 4; j++) split3(s[kq * 4 + j][onl], q0[j], q1[j], q2[j]);
    size_t base = (size_t)(n0 + onl) * K_pad + k0 + kq * 4;
    *(uint2*)(colh + base)                   = make_uint2(pack2(q0[0], q0[1]), pack2(q0[2], q0[3]));
    *(uint2*)(colh + planeStride + base)     = make_uint2(pack2(q1[0], q1[1]), pack2(q1[2], q1[3]));
    *(uint2*)(colh + 2 * planeStride + base) = make_uint2(pack2(q2[0], q2[1]), pack2(q2[2], q2[3]));
}

// ---------------------------------------------------------------------------
// unified weight prep (single launch). Conv layers reordered rs-major.
// ---------------------------------------------------------------------------
struct PrepArgs {
    const float* w[11];
    const float* dt1;
    const float* dt2;
};

__global__ void prep_weights(PrepArgs pa, __nv_bfloat16* __restrict__ wtsh,
                             float* __restrict__ wpk)
{
    const int y = blockIdx.y;
    const int i = blockIdx.x * 256 + threadIdx.x;
    if (y < 11) {
        const int Ks[11] = {48, 4096, 2304, 256, 2304, 256, 2304, 256, 2304, 256, 256};
        const int Kp[11] = {64, 4096, 2304, 256, 2304, 256, 2304, 256, 2304, 256, 256};
        const int Ms[11] = {256, 256, 256, 256, 256, 256, 256, 256, 256, 256, 512};
        const int RSs[11] = {0, 16, 9, 0, 9, 0, 9, 0, 9, 0, 0};  // 0 = direct
        const int Of[11] = {OFF_C1, OFF_C2, OFF_ER1A, OFF_ER1B, OFF_ER2A, OFF_ER2B,
                            OFF_DR1A, OFF_DR1B, OFF_DR2A, OFF_DR2B, OFF_EMB};
        int K = Ks[y], K_pad = Kp[y], M = Ms[y], RS = RSs[y], off = Of[y];
        if (i >= M * K_pad) return;
        int m = i / K_pad, k = i - m * K_pad;
        float v;
        if (RS > 0) {
            int ci = k & 255, rs = k >> 8;
            v = pa.w[y][m * K + ci * RS + rs];
        } else {
            v = (k < K) ? pa.w[y][m * K + k] : 0.f;
        }
        uint16_t q0, q1, q2;
        split3(v, q0, q1, q2);
        wtsh[off + i] = __ushort_as_bfloat16(q0);
        wtsh[WPLANE + off + i] = __ushort_as_bfloat16(q1);
        wtsh[2 * WPLANE + off + i] = __ushort_as_bfloat16(q2);
    } else if (y < 15) {
        if (i >= 262144) return;
        int par = y - 11;
        int ry = par >> 1, rx = par & 1;
        int co = i >> 10;
        int k = i & 1023;
        int ci = k & 255, tap = k >> 8;      // tap-major
        int a = tap >> 1, bb = tap & 1;
        float v = pa.dt1[((ci * 256 + co) * 4 + (3 - ry - 2 * a)) * 4 + (3 - rx - 2 * bb)];
        uint16_t q0, q1, q2;
        split3(v, q0, q1, q2);
        int off = OFF_DT1 + par * 262144;
        wtsh[off + i] = __ushort_as_bfloat16(q0);
        wtsh[WPLANE + off + i] = __ushort_as_bfloat16(q1);
        wtsh[2 * WPLANE + off + i] = __ushort_as_bfloat16(q2);
    } else {
        if (i >= 12288) return;
        int tap = i & 3;
        int par = (i >> 2) & 3;
        int co = (i >> 4) % 3;
        int ci = i / 48;
        int a = tap >> 1, bb = tap & 1;
        int ry = par >> 1, rx = par & 1;
        wpk[i] = pa.dt2[((ci * 3 + co) * 4 + (3 - ry - 2 * a)) * 4 + (3 - rx - 2 * bb)];
    }
}

// ---------------------------------------------------------------------------
// VQ kernels
// ---------------------------------------------------------------------------
__global__ void vq_enorm(const float* __restrict__ e, float* __restrict__ en)
{
    __shared__ float s[256];
    int k = blockIdx.x;
    float v = e[k * 256 + threadIdx.x];
    s[threadIdx.x] = v * v;
    __syncthreads();
    for (int off = 128; off > 0; off >>= 1) {
        if (threadIdx.x < off) s[threadIdx.x] += s[threadIdx.x + off];
        __syncthreads();
    }
    if (threadIdx.x == 0) en[k] = s[0];
}

__global__ void vq_argmin(const float* __restrict__ S, const float* __restrict__ en,
                          int* __restrict__ idx)
{
    int n = blockIdx.x * 256 + threadIdx.x;
    if (n >= N_LAT) return;
    float best = 3.4e38f;
    int bi = 0;
    for (int k = 0; k < 512; k++) {
        float v = en[k] - 2.f * S[k * N_LAT + n];
        if (v < best) { best = v; bi = k; }
    }
    idx[n] = bi;
}

// gather z_q: NHWC fp32 + 2-plane NHWC bf16, deterministic loss partials
__global__ void vq_gather(const float* __restrict__ zef, const float* __restrict__ embed,
                          const int* __restrict__ idx, float* __restrict__ zqf,
                          __nv_bfloat16* __restrict__ zqh, size_t ps,
                          float* __restrict__ part)
{
    __shared__ float s[8];
    int warp = threadIdx.x >> 5, lane = threadIdx.x & 31;
    int n = blockIdx.x * 8 + warp;
    int id = idx[n];
    float acc = 0.f;
    for (int d = lane; d < 256; d += 32) {
        float e = embed[id * 256 + d];
        float z = zef[(size_t)n * 256 + d];
        zqf[(size_t)n * 256 + d] = e;
        uint16_t q0, q1;
        split2(e, q0, q1);
        zqh[(size_t)n * 256 + d] = __ushort_as_bfloat16(q0);
        zqh[ps + (size_t)n * 256 + d] = __ushort_as_bfloat16(q1);
        float df = z - e;
        acc += df * df;
    }
#pragma unroll
    for (int off = 16; off > 0; off >>= 1)
        acc += __shfl_xor_sync(0xffffffffu, acc, off);
    if (lane == 0) s[warp] = acc;
    __syncthreads();
    if (threadIdx.x == 0) {
        float v = 0.f;
        for (int w = 0; w < 8; w++) v += s[w];
        part[blockIdx.x] = v;
    }
}

__global__ void loss_write(const float* __restrict__ part, float* __restrict__ out, int out_size)
{
    __shared__ float s[256];
    float v = 0.f;
    for (int i = threadIdx.x; i < 4096; i += 256) v += part[i];
    s[threadIdx.x] = v;
    __syncthreads();
    for (int off = 128; off > 0; off >>= 1) {
        if (threadIdx.x < off) s[threadIdx.x] += s[threadIdx.x + off];
        __syncthreads();
    }
    if (threadIdx.x == 0 && out_size >= 2) {
        float L = s[0] / 32768.f;
        out[out_size - 2] = L;
        out[out_size - 1] = L;
    }
}

// ---------------------------------------------------------------------------
// deconv2 (256 -> 3, k4 s2 p1) + sigmoid, direct parity kernel (d1 NCHW fp32).
// ---------------------------------------------------------------------------
__global__ __launch_bounds__(256) void deconv2_sig(
    const float* __restrict__ in, const float* __restrict__ wpk,
    const float* __restrict__ bias, float* __restrict__ out)
{
    __shared__ float ins[2][34][36];
    __shared__ float wsc[96];
    const int tid = threadIdx.x;
    const int b = blockIdx.y;
    const int tileY = (blockIdx.x >> 1) << 5;
    const int tileX = (blockIdx.x & 1) << 5;
    const int lmy = (tid >> 4) << 1;
    const int lmx = (tid & 15) << 1;

    float acc[48];
#pragma unroll
    for (int i = 0; i < 48; i++) acc[i] = 0.f;

    const float* inb = in + (size_t)b * 256 * 4096;

    for (int c0 = 0; c0 < 256; c0 += 2) {
        __syncthreads();
        for (int e = tid; e < 2 * 34 * 34; e += 256) {
            int cc = (e >= 1156) ? 1 : 0;
            int rem = e - cc * 1156;
            int r = rem / 34, c = rem - r * 34;
            int gy = tileY - 1 + r, gx = tileX - 1 + c;
            float v = 0.f;
            if ((unsigned)gy < 64u && (unsigned)gx < 64u)
                v = inb[(c0 + cc) * 4096 + (gy << 6) + gx];
            ins[cc][r][c] = v;
        }
        if (tid < 96) wsc[tid] = wpk[c0 * 48 + tid];
        __syncthreads();
#pragma unroll
        for (int cc = 0; cc < 2; cc++) {
            float r4[4][4];
#pragma unroll
            for (int dy = 0; dy < 4; dy++)
#pragma unroll
                for (int dx = 0; dx < 4; dx++)
                    r4[dy][dx] = ins[cc][lmy + dy][lmx + dx];
#pragma unroll
            for (int co = 0; co < 3; co++)
#pragma unroll
                for (int par = 0; par < 4; par++) {
                    int ry = par >> 1, rx = par & 1;
                    float4 w = *(const float4*)&wsc[cc * 48 + co * 16 + par * 4];
#pragma unroll
                    for (int dmy = 0; dmy < 2; dmy++)
#pragma unroll
                        for (int dmx = 0; dmx < 2; dmx++) {
                            acc[((dmy * 2 + dmx) * 3 + co) * 4 + par] +=
                                  w.x * r4[dmy + ry][dmx + rx]
                                + w.y * r4[dmy + ry][dmx + 1 + rx]
                                + w.z * r4[dmy + 1 + ry][dmx + rx]
                                + w.w * r4[dmy + 1 + ry][dmx + 1 + rx];
                        }
                }
        }
    }

#pragma unroll
    for (int dmy = 0; dmy < 2; dmy++)
#pragma unroll
        for (int dmx = 0; dmx < 2; dmx++)
#pragma unroll
            for (int co = 0; co < 3; co++)
#pragma unroll
                for (int par = 0; par < 4; par++) {
                    int ry = par >> 1, rx = par & 1;
                    int my = tileY + lmy + dmy, mx = tileX + lmx + dmx;
                    int oy = (my << 1) + ry, ox = (mx << 1) + rx;
                    float v = acc[((dmy * 2 + dmx) * 3 + co) * 4 + par] + bias[co];
                    v = 1.f / (1.f + expf(-v));
                    out[((b * 3 + co) << 14) + (oy << 7) + ox] = v;
                }
}

// ---------------------------------------------------------------------------
// launcher
// ---------------------------------------------------------------------------
extern "C" void kernel_launch(void* const* d_in, const int* in_sizes, int n_in,
                              void* d_out, int out_size)
{
    const float* x     = (const float*)d_in[0];
    const float* embed = (const float*)d_in[1];
    const float* dt1_b = (const float*)d_in[13];
    const float* dt2_b = (const float*)d_in[15];
    float* out = (float*)d_out;

    __nv_bfloat16 *colh, *wtsh;
    float *h2f, *abf, *zef, *zqf, *bbf, *S, *d1, *enrm, *wpk, *part;
    int* idxp;
    cudaGetSymbolAddress((void**)&colh, g_colh);
    cudaGetSymbolAddress((void**)&wtsh, g_wtsh);
    cudaGetSymbolAddress((void**)&h2f,  g_h2);
    cudaGetSymbolAddress((void**)&abf,  g_a);
    cudaGetSymbolAddress((void**)&zef,  g_ze);
    cudaGetSymbolAddress((void**)&zqf,  g_zq);
    cudaGetSymbolAddress((void**)&bbf,  g_b2);
    cudaGetSymbolAddress((void**)&S,    g_s);
    cudaGetSymbolAddress((void**)&d1,   g_d1);
    cudaGetSymbolAddress((void**)&enrm, g_enorm);
    cudaGetSymbolAddress((void**)&wpk,  g_wpk);
    cudaGetSymbolAddress((void**)&part, g_part);
    cudaGetSymbolAddress((void**)&idxp, g_idx);

    cudaFuncSetAttribute(gemm_imp, cudaFuncAttributeMaxDynamicSharedMemorySize, GEMM_SMEM_H);

    // ---- weight prep ----
    PrepArgs pa;
    pa.w[0]  = (const float*)d_in[2];
    pa.w[1]  = (const float*)d_in[3];
    pa.w[2]  = (const float*)d_in[4];
    pa.w[3]  = (const float*)d_in[5];
    pa.w[4]  = (const float*)d_in[6];
    pa.w[5]  = (const float*)d_in[7];
    pa.w[6]  = (const float*)d_in[8];
    pa.w[7]  = (const float*)d_in[9];
    pa.w[8]  = (const float*)d_in[10];
    pa.w[9]  = (const float*)d_in[11];
    pa.w[10] = embed;
    pa.dt1   = (const float*)d_in[12];
    pa.dt2   = (const float*)d_in[14];
    prep_weights<<<dim3(4096, 16), 256>>>(pa, wtsh, wpk);

    // ---- conv1: im2col (C=3, K=48->64) then 1x1-style GEMM -> h1h NHWC ----
    im2colT_conv_h<<<dim3(N_HALF / 32, 2), 256>>>(x, colh + COLA, PS_LAT,
        3, 128, 128, 12, 6, 16, 4, 2, 1, 48, 64);
    gemm_imp<<<dim3(2, N_HALF / 128), 512, GEMM_SMEM_H>>>(
        wtsh + OFF_C1, WPLANE, colh + COLA, PS_LAT,
        256, 64, 1, 64, 1, 1, 0, 0, 1, 64, 64, 12, 6,
        0, colh + H1H, PS_H1, 2, nullptr, nullptr, nullptr, 1,
        0, 0, 0, 0, 0, 0);

    // ---- conv2: implicit k4 s2 p1 over h1h -> h2h + h2f, relu ----
    gemm_imp<<<dim3(2, N_LAT / 128), 512, GEMM_SMEM_H>>>(
        wtsh + OFF_C2, WPLANE, colh + H1H, PS_H1,
        256, 4096, 0, 256, 3, 4, -1, -1, 2, 64, 64, 10, 5,
        0, colh + H2H, PS_LAT, 2, h2f, nullptr, nullptr, 1,
        0, 0, 0, 0, 0, 0);

    // ---- residual block helper ----
    auto res = [&](size_t srch, const float* srcf, int offA, int offB,
                   size_t outh, int outPl, float* outf) {
        // 3x3 relu -> tmph
        gemm_imp<<<dim3(2, N_LAT / 128), 512, GEMM_SMEM_H>>>(
            wtsh + offA, WPLANE, colh + srch, PS_LAT,
            256, 2304, 0, 256, 3, 3, -1, -1, 1, 32, 32, 10, 5,
            0, colh + TMPH, PS_LAT, 2, nullptr, nullptr, nullptr, 1,
            0, 0, 0, 0, 0, 0);
        // 1x1 + resid -> out
        gemm_imp<<<dim3(2, N_LAT / 128), 512, GEMM_SMEM_H>>>(
            wtsh + offB, WPLANE, colh + TMPH, PS_LAT,
            256, 256, 0, 256, 3, 1, 0, 0, 1, 32, 32, 10, 5,
            0, colh + outh, PS_LAT, outPl, outf, srcf, nullptr, 0,
            0, 0, 0, 0, 0, 0);
    };
    res(H2H, h2f, OFF_ER1A, OFF_ER1B, ABH, 2, abf);
    res(ABH, abf, OFF_ER2A, OFF_ER2B, ZEH, 3, zef);

    // ---- VQ scores: full-precision GEMM over zeh (3-plane), rowmajor out ----
    // B treated as a 1 x N_LAT "image" (Hin=1, Win=N_LAT) so the loader's
    // pixel decode matches the epilogue's rowmajor decode (logHWo=logWo=15).
    vq_enorm<<<512, 256>>>(embed, enrm);
    gemm_imp<<<dim3(4, N_LAT / 128), 512, GEMM_SMEM_H>>>(
        wtsh + OFF_EMB, WPLANE, colh + ZEH, PS_LAT,
        512, 256, 1, 256, 3, 1, 0, 0, 1, 1, N_LAT, 15, 15,
        1, nullptr, 0, 0, S, nullptr, nullptr, 0,
        1, N_LAT, 1, 1, 0, 0);
    vq_argmin<<<N_LAT / 256, 256>>>(S, enrm, idxp);
    vq_gather<<<4096, 256>>>(zef, embed, idxp, zqf, colh + ZQH, PS_LAT, part);

    // ---- decoder residual blocks ----
    res(ZQH, zqf, OFF_DR1A, OFF_DR1B, ABH, 2, abf);
    res(ABH, abf, OFF_DR2A, OFF_DR2B, BBH, 2, bbf);

    // ---- deconv1: 4 parity implicit GEMMs, NCHW scatter + bias + relu ----
    for (int par = 0; par < 4; par++) {
        int ry = par >> 1, rx = par & 1;
        gemm_imp<<<dim3(2, N_LAT / 128), 512, GEMM_SMEM_H>>>(
            wtsh + OFF_DT1 + par * 262144, WPLANE, colh + BBH, PS_LAT,
            256, 1024, 0, 256, 3, 2, ry - 1, rx - 1, 1, 32, 32, 10, 5,
            1, nullptr, 0, 0, d1, nullptr, dt1_b, 1,
            64, 64, 2, 2, ry, rx);
    }

    // ---- deconv2 + sigmoid ----
    deconv2_sig<<<dim3(4, 32), 256>>>(d1, wpk, dt2_b, out);

    // ---- losses ----
    loss_write<<<1, 256>>>(part, out, out_size);
}